// round 16
// baseline (speedup 1.0000x reference)
#include <cuda_runtime.h>
#include <cuda_fp16.h>
#include <math.h>
#include <stdint.h>

#define LQ      37440
#define LIN     37440
#define DM      256
#define NHEADS  8
#define CHEAD   32

// scratch (allocation-free per harness rules)
__device__ __half  g_value_h  [LIN * DM];     // [Lin, 256] half (sampler gathers)
__device__ __half  g_oa_h     [LQ * 512];     // [Lq, off(384) | attn(128)] half
__device__ __half  g_inflat_h [LIN * DM];     // inflat as half
__device__ __half  g_query_h  [LQ * DM];      // query as half
__device__ __half  g_sampled_h[LQ * DM];      // sampler output as half
__device__ uint32_t g_wv2   [128 * 256];      // W_value  k-pair-interleaved half2
__device__ uint32_t g_woa2  [128 * 512];      // [W_off|W_attn] interleaved half2
__device__ uint32_t g_wout2 [128 * 256];      // W_out interleaved half2
__device__ float   g_boa    [512];            // [b_off ; b_attn]

__device__ __forceinline__ uint32_t pack_h2(float lo, float hi) {
    __half2 h = __floats2half2_rn(lo, hi);
    return *(uint32_t*)&h;
}
__device__ __forceinline__ uint32_t smem_u32(const void* p) {
    uint32_t a;
    asm("{ .reg .u64 t; cvta.to.shared.u64 t, %1; cvt.u32.u64 %0, t; }"
        : "=r"(a) : "l"(p));
    return a;
}
__device__ __forceinline__ void cp_async16(uint32_t dst, const void* src, int srcb) {
    asm volatile("cp.async.cg.shared.global [%0], [%1], 16, %2;"
                 :: "r"(dst), "l"(src), "r"(srcb) : "memory");
}

#define MMA_F16(d, a, b)                                                      \
    asm volatile(                                                             \
        "mma.sync.aligned.m16n8k16.row.col.f32.f16.f16.f32 "                  \
        "{%0,%1,%2,%3}, {%4,%5,%6,%7}, {%8,%9}, {%0,%1,%2,%3};"               \
        : "+f"((d)[0]), "+f"((d)[1]), "+f"((d)[2]), "+f"((d)[3])              \
        : "r"((a)[0]), "r"((a)[1]), "r"((a)[2]), "r"((a)[3]),                 \
          "r"((b)[0]), "r"((b)[1]))

#define PA 20     // A pitch in half2 words (16 + 4) -> conflict-free frags
#define PB 136    // B pitch in half2 words (128 + 8) -> conflict-free frags

// ---------------------------------------------------------------------------
// shared GEMM body: 2-stage cp.async fp16 pipeline (proven R11/R13).
// ---------------------------------------------------------------------------
struct GemmSmem {
    uint32_t As2[2][128 * PA];   // 20.0 KB
    uint32_t Bs2[2][16 * PB];    // 17.0 KB
};

__device__ __forceinline__ void gemm_mainloop(
    GemmSmem* sm, const __half* __restrict__ A, const uint32_t* __restrict__ B2,
    int M, int N, int bm, int bn, float acc[4][4][4])
{
    const int tid  = threadIdx.x;
    const int wid  = tid >> 5;
    const int lane = tid & 31;
    const int g    = lane >> 2;
    const int tg   = lane & 3;
    const int warp_m = (wid >> 2) * 64;
    const int warp_n = (wid & 3) * 32;

    const uint32_t sA = smem_u32(sm->As2);
    const uint32_t sB = smem_u32(sm->Bs2);

    const int amr[2] = { (tid)      >> 2, (tid + 256) >> 2 };
    const int ac4[2] = { (tid & 3) * 4,  (tid & 3) * 4 };
    const int bkr[2] = { (tid)      >> 5, (tid + 256) >> 5 };
    const int bn4[2] = { (tid & 31) * 4, (tid & 31) * 4 };

    #define ISSUE(T, BUF)                                                     \
    do {                                                                      \
        _Pragma("unroll")                                                     \
        for (int i = 0; i < 2; i++) {                                         \
            int gm = bm + amr[i];                                             \
            int srcb = (gm < M) ? 16 : 0;                                     \
            int gmc = (gm < M) ? gm : (M - 1);                                \
            cp_async16(sA + ((BUF) * (128 * PA) + amr[i] * PA + ac4[i]) * 4,  \
                       A + (size_t)gmc * 256 + (T) * 32 + ac4[i] * 2, srcb);  \
            cp_async16(sB + ((BUF) * (16 * PB) + bkr[i] * PB + bn4[i]) * 4,   \
                       B2 + (size_t)((T) * 16 + bkr[i]) * N + bn + bn4[i],    \
                       16);                                                   \
        }                                                                     \
        asm volatile("cp.async.commit_group;" ::: "memory");                  \
    } while (0)

    ISSUE(0, 0);

    #pragma unroll 1
    for (int t = 0; t < 8; t++) {
        if (t < 7) {
            ISSUE(t + 1, (t + 1) & 1);
            asm volatile("cp.async.wait_group 1;" ::: "memory");
        } else {
            asm volatile("cp.async.wait_group 0;" ::: "memory");
        }
        __syncthreads();

        const uint32_t* as = sm->As2[t & 1];
        const uint32_t* bs = sm->Bs2[t & 1];
        #pragma unroll
        for (int ks = 0; ks < 2; ks++) {
            const int kb = ks * 8;
            uint32_t afr[4][4], bfr[4][2];
            #pragma unroll
            for (int mi = 0; mi < 4; mi++) {
                int rb = warp_m + mi * 16 + g;
                afr[mi][0] = as[(rb)     * PA + tg + kb];
                afr[mi][1] = as[(rb + 8) * PA + tg + kb];
                afr[mi][2] = as[(rb)     * PA + tg + 4 + kb];
                afr[mi][3] = as[(rb + 8) * PA + tg + 4 + kb];
            }
            #pragma unroll
            for (int ni = 0; ni < 4; ni++) {
                int col = warp_n + ni * 8 + g;
                bfr[ni][0] = bs[(tg + kb)     * PB + col];
                bfr[ni][1] = bs[(tg + 4 + kb) * PB + col];
            }
            #pragma unroll
            for (int mi = 0; mi < 4; mi++)
                #pragma unroll
                for (int ni = 0; ni < 4; ni++)
                    MMA_F16(acc[mi][ni], afr[mi], bfr[ni]);
        }
        __syncthreads();
    }
    #undef ISSUE
}

__device__ __forceinline__ void gemm_epilogue(
    const float* __restrict__ bias, void* __restrict__ C,
    int M, int N, int bm, int bn, bool half_out, float acc[4][4][4])
{
    const int tid  = threadIdx.x;
    const int wid  = tid >> 5;
    const int lane = tid & 31;
    const int g    = lane >> 2;
    const int tg   = lane & 3;
    const int warp_m = (wid >> 2) * 64;
    const int warp_n = (wid & 3) * 32;

    #pragma unroll
    for (int ni = 0; ni < 4; ni++) {
        const int col = bn + warp_n + ni * 8 + tg * 2;
        const float b0 = bias[col], b1 = bias[col + 1];
        #pragma unroll
        for (int mi = 0; mi < 4; mi++) {
            int r0 = bm + warp_m + mi * 16 + g;
            if (r0 < M) {
                if (half_out)
                    *(uint32_t*)((__half*)C + (size_t)r0 * N + col) =
                        pack_h2(acc[mi][ni][0] + b0, acc[mi][ni][1] + b1);
                else
                    *(float2*)((float*)C + (size_t)r0 * N + col) =
                        make_float2(acc[mi][ni][0] + b0, acc[mi][ni][1] + b1);
            }
            int r1 = r0 + 8;
            if (r1 < M) {
                if (half_out)
                    *(uint32_t*)((__half*)C + (size_t)r1 * N + col) =
                        pack_h2(acc[mi][ni][2] + b0, acc[mi][ni][3] + b1);
                else
                    *(float2*)((float*)C + (size_t)r1 * N + col) =
                        make_float2(acc[mi][ni][2] + b0, acc[mi][ni][3] + b1);
            }
        }
    }
}

// combined front GEMM: blocks x<2 -> value GEMM (N=256), x>=2 -> oa (N=512).
// Both outputs half.
__global__ __launch_bounds__(256, 2) void gemm_front(
    const __half* __restrict__ A1, const uint32_t* __restrict__ B1,
    const float* __restrict__ bias1, __half* __restrict__ C1,
    const __half* __restrict__ A2, const uint32_t* __restrict__ B2,
    const float* __restrict__ bias2, __half* __restrict__ C2)
{
    __shared__ GemmSmem sm;
    const bool first = (blockIdx.x < 2);
    const __half*   A    = first ? A1 : A2;
    const uint32_t* B    = first ? B1 : B2;
    const float*    bias = first ? bias1 : bias2;
    void*           C    = first ? (void*)C1 : (void*)C2;
    const int       N    = first ? 256 : 512;
    const int       bn   = (first ? blockIdx.x : (blockIdx.x - 2)) * 128;
    const int       bm   = blockIdx.y * 128;
    const int       M    = LQ;

    float acc[4][4][4];
    #pragma unroll
    for (int i = 0; i < 4; i++)
        #pragma unroll
        for (int j = 0; j < 4; j++)
            #pragma unroll
            for (int r = 0; r < 4; r++) acc[i][j][r] = 0.f;

    gemm_mainloop(&sm, A, B, M, N, bm, bn, acc);
    gemm_epilogue(bias, C, M, N, bm, bn, true, acc);
}

// out GEMM (fp32 out, N=256)
__global__ __launch_bounds__(256, 2) void gemm_out(
    const __half* __restrict__ A, const uint32_t* __restrict__ B2,
    const float* __restrict__ bias, float* __restrict__ C)
{
    __shared__ GemmSmem sm;
    const int bn = blockIdx.x * 128;
    const int bm = blockIdx.y * 128;

    float acc[4][4][4];
    #pragma unroll
    for (int i = 0; i < 4; i++)
        #pragma unroll
        for (int j = 0; j < 4; j++)
            #pragma unroll
            for (int r = 0; r < 4; r++) acc[i][j][r] = 0.f;

    gemm_mainloop(&sm, A, B2, LQ, 256, bm, bn, acc);
    gemm_epilogue(bias, C, LQ, 256, bm, bn, false, acc);
}

// ---------------------------------------------------------------------------
// fused prep kernels
// ---------------------------------------------------------------------------
__global__ __launch_bounds__(256) void f2h_all(
    const float* __restrict__ inflat, const float* __restrict__ query,
    __half* __restrict__ d_inflat, __half* __restrict__ d_query, int n4)
{
    int i = blockIdx.x * 256 + threadIdx.x;
    if (i < n4) {
        float4 v = ((const float4*)inflat)[i];
        ((uint2*)d_inflat)[i] = make_uint2(pack_h2(v.x, v.y), pack_h2(v.z, v.w));
    } else if (i < 2 * n4) {
        int j = i - n4;
        float4 v = ((const float4*)query)[j];
        ((uint2*)d_query)[j] = make_uint2(pack_h2(v.x, v.y), pack_h2(v.z, v.w));
    }
}

__global__ __launch_bounds__(256) void pack_all(
    const float* __restrict__ W_value, const float* __restrict__ W_out,
    const float* __restrict__ W_off,   const float* __restrict__ W_attn,
    const float* __restrict__ b_off,   const float* __restrict__ b_attn,
    uint32_t* __restrict__ wv2, uint32_t* __restrict__ wout2,
    uint32_t* __restrict__ woa2, float* __restrict__ boa)
{
    int i = blockIdx.x * 256 + threadIdx.x;
    if (i < 32768) {                       // W_value: [128][256]
        int k2 = i >> 8, n = i & 255;
        wv2[i] = pack_h2(W_value[(size_t)(2 * k2) * 256 + n],
                         W_value[(size_t)(2 * k2 + 1) * 256 + n]);
    } else if (i < 65536) {                // W_out: [128][256]
        int j = i - 32768;
        int k2 = j >> 8, n = j & 255;
        wout2[j] = pack_h2(W_out[(size_t)(2 * k2) * 256 + n],
                           W_out[(size_t)(2 * k2 + 1) * 256 + n]);
    } else if (i < 131072) {               // W_off|W_attn: [128][512]
        int j = i - 65536;
        int k2 = j >> 9, n = j & 511;
        float a, b;
        if (n < 384) {
            a = W_off[(size_t)(2 * k2) * 384 + n];
            b = W_off[(size_t)(2 * k2 + 1) * 384 + n];
        } else {
            a = W_attn[(size_t)(2 * k2) * 128 + n - 384];
            b = W_attn[(size_t)(2 * k2 + 1) * 128 + n - 384];
        }
        woa2[j] = pack_h2(a, b);
    } else if (i < 131584) {               // bias concat
        int j = i - 131072;
        boa[j] = (j < 384) ? b_off[j] : b_attn[j - 384];
    }
}

// ---------------------------------------------------------------------------
// Sampling: 2 queries/block; dual-query interleaved gather (R13).
// oa is HALF now; phase-1 corner list stored via 4x STS.128 per thread with
// slot remap [h][c2*32 + p*2 + (c&1)] (gather reads all slots linearly, so
// placement is arbitrary; summation order irrelevant).
// ---------------------------------------------------------------------------
__global__ __launch_bounds__(256) void sample_kernel(
    const __half* __restrict__ value,   // [Lin, 256] half
    const float* __restrict__ refpts,   // [Lq, 4, 3]
    const __half* __restrict__ oa,      // [Lq, 512] half: off 0..383, attn 384..511
    __half* __restrict__ sampled)       // [Lq, 256] half
{
    const int q0  = blockIdx.x * 2;
    const int tid = threadIdx.x;
    const unsigned FULL = 0xffffffffu;

    __shared__ float2 s_cwi[2][128 * 8];   // [qi][h*128 + slot]

    {
        const int qi = tid >> 7;
        const int t  = tid & 127;
        const int q  = q0 + qi;
        const int h  = t >> 4;
        const int p  = t & 15;
        const int l  = p >> 2;
        const int pt = p & 3;

        float logit = __half2float(oa[(size_t)q * 512 + 384 + t]);
        float mx = logit;
        #pragma unroll
        for (int m = 8; m; m >>= 1)
            mx = fmaxf(mx, __shfl_xor_sync(FULL, mx, m));
        float e = __expf(logit - mx);
        float sum = e;
        #pragma unroll
        for (int m = 8; m; m >>= 1)
            sum += __shfl_xor_sync(FULL, sum, m);
        const float wp = e / sum;

        const int   S     = 32 >> l;
        const int   start = (l == 0) ? 0 : (l == 1) ? 32768
                          : (l == 2) ? 36864 : 37376;
        const float fS    = (float)S;

        const float rx = refpts[(size_t)q * 12 + l * 3 + 0];
        const float ry = refpts[(size_t)q * 12 + l * 3 + 1];
        const float rz = refpts[(size_t)q * 12 + l * 3 + 2];

        const size_t ob = (size_t)q * 512 + h * 48 + l * 12 + pt * 3;
        const float o0 = __half2float(oa[ob + 0]);
        const float o1 = __half2float(oa[ob + 1]);
        const float o2 = __half2float(oa[ob + 2]);
        const float ix = fmaf(rx, fS, o0 - 0.5f);
        const float iy = fmaf(ry, fS, o1 - 0.5f);
        const float iz = fmaf(rz, fS, o2 - 0.5f);

        const float x0f = floorf(ix), y0f = floorf(iy), z0f = floorf(iz);
        const float fx = ix - x0f, fy = iy - y0f, fz = iz - z0f;
        const int x0 = (int)x0f, y0 = (int)y0f, z0 = (int)z0f;

        const float wxv[2] = {1.f - fx, fx};
        const float wyv[2] = {1.f - fy, fy};
        const float wzv[2] = {1.f - fz, fz};

        float2 tmp[8];
        #pragma unroll
        for (int c = 0; c < 8; c++) {
            const int xc = x0 + (c & 1);
            const int yc = y0 + ((c >> 1) & 1);
            const int zc = z0 + (c >> 2);
            const bool valid = ((unsigned)xc < (unsigned)S) &
                               ((unsigned)yc < (unsigned)S) &
                               ((unsigned)zc < (unsigned)S);
            float w  = valid ? wp * wzv[c >> 2] * wyv[(c >> 1) & 1] * wxv[c & 1]
                             : 0.f;
            int  idx = valid ? (start + (zc * S + yc) * S + xc) * DM : 0;
            tmp[c] = make_float2(w, __int_as_float(idx));
        }

        float2* base = &s_cwi[qi][h * 128 + p * 2];
        #pragma unroll
        for (int c2 = 0; c2 < 4; c2++)
            *(float4*)(base + c2 * 32) =
                make_float4(tmp[2 * c2].x,     tmp[2 * c2].y,
                            tmp[2 * c2 + 1].x, tmp[2 * c2 + 1].y);
    }
    __syncthreads();

    const int h    = tid >> 5;
    const int lane = tid & 31;
    const int grp  = lane >> 3;
    const int cg   = lane & 7;
    const __half* vbase = value + h * CHEAD + cg * 4;

    const float2* cw0 = s_cwi[0] + h * 128 + grp;
    const float2* cw1 = s_cwi[1] + h * 128 + grp;

    float a0x = 0.f, a0y = 0.f, a0z = 0.f, a0w = 0.f;
    float a1x = 0.f, a1y = 0.f, a1z = 0.f, a1w = 0.f;

    #pragma unroll 4
    for (int j = 0; j < 32; j++) {
        float2 e0 = cw0[j * 4];
        float2 e1 = cw1[j * 4];
        if (e0.x != 0.f) {
            uint2 u = *(const uint2*)(vbase + __float_as_int(e0.y));
            float2 v0 = __half22float2(*(__half2*)&u.x);
            float2 v1 = __half22float2(*(__half2*)&u.y);
            a0x = fmaf(e0.x, v0.x, a0x);
            a0y = fmaf(e0.x, v0.y, a0y);
            a0z = fmaf(e0.x, v1.x, a0z);
            a0w = fmaf(e0.x, v1.y, a0w);
        }
        if (e1.x != 0.f) {
            uint2 u = *(const uint2*)(vbase + __float_as_int(e1.y));
            float2 v0 = __half22float2(*(__half2*)&u.x);
            float2 v1 = __half22float2(*(__half2*)&u.y);
            a1x = fmaf(e1.x, v0.x, a1x);
            a1y = fmaf(e1.x, v0.y, a1y);
            a1z = fmaf(e1.x, v1.x, a1z);
            a1w = fmaf(e1.x, v1.y, a1w);
        }
    }

    #pragma unroll
    for (int m = 8; m <= 16; m <<= 1) {
        a0x += __shfl_xor_sync(FULL, a0x, m);
        a0y += __shfl_xor_sync(FULL, a0y, m);
        a0z += __shfl_xor_sync(FULL, a0z, m);
        a0w += __shfl_xor_sync(FULL, a0w, m);
        a1x += __shfl_xor_sync(FULL, a1x, m);
        a1y += __shfl_xor_sync(FULL, a1y, m);
        a1z += __shfl_xor_sync(FULL, a1z, m);
        a1w += __shfl_xor_sync(FULL, a1w, m);
    }
    if (lane < 8) {
        *(uint2*)(sampled + (size_t)q0 * DM + h * CHEAD + cg * 4)
            = make_uint2(pack_h2(a0x, a0y), pack_h2(a0z, a0w));
        *(uint2*)(sampled + (size_t)(q0 + 1) * DM + h * CHEAD + cg * 4)
            = make_uint2(pack_h2(a1x, a1y), pack_h2(a1z, a1w));
    }
}

// ---------------------------------------------------------------------------
extern "C" void kernel_launch(void* const* d_in, const int* in_sizes, int n_in,
                              void* d_out, int out_size)
{
    const float* query   = (const float*)d_in[0];
    const float* refpts  = (const float*)d_in[1];
    const float* inflat  = (const float*)d_in[2];
    const float* W_value = (const float*)d_in[5];
    const float* b_value = (const float*)d_in[6];
    const float* W_off   = (const float*)d_in[7];
    const float* b_off   = (const float*)d_in[8];
    const float* W_attn  = (const float*)d_in[9];
    const float* b_attn  = (const float*)d_in[10];
    const float* W_out   = (const float*)d_in[11];
    const float* b_out   = (const float*)d_in[12];
    float* out = (float*)d_out;

    float *p_boa;
    __half *p_value_h, *p_oa_h, *p_inflat_h, *p_query_h, *p_sampled_h;
    uint32_t *p_wv2, *p_woa2, *p_wout2;
    cudaGetSymbolAddress((void**)&p_value_h,   g_value_h);
    cudaGetSymbolAddress((void**)&p_oa_h,      g_oa_h);
    cudaGetSymbolAddress((void**)&p_inflat_h,  g_inflat_h);
    cudaGetSymbolAddress((void**)&p_query_h,   g_query_h);
    cudaGetSymbolAddress((void**)&p_sampled_h, g_sampled_h);
    cudaGetSymbolAddress((void**)&p_wv2,       g_wv2);
    cudaGetSymbolAddress((void**)&p_woa2,      g_woa2);
    cudaGetSymbolAddress((void**)&p_wout2,     g_wout2);
    cudaGetSymbolAddress((void**)&p_boa,       g_boa);

    const int n4 = LIN * DM / 4;   // 2396160

    f2h_all<<<(2 * n4 + 255) / 256, 256>>>(inflat, query, p_inflat_h, p_query_h, n4);
    pack_all<<<(131584 + 255) / 256, 256>>>(W_value, W_out, W_off, W_attn,
                                            b_off, b_attn,
                                            p_wv2, p_wout2, p_woa2, p_boa);

    const int mb = (LQ + 127) / 128;      // 293

    // value GEMM (half out) + oa GEMM (half out) in one launch
    gemm_front<<<dim3(6, mb), 256>>>(p_inflat_h, p_wv2, b_value, p_value_h,
                                     p_query_h, p_woa2, p_boa, p_oa_h);
    // softmax + trilinear sampling -> half         [Lq, 256]
    sample_kernel<<<LQ / 2, 256>>>(p_value_h, refpts, p_oa_h, p_sampled_h);
    // out = sampled @ W_out + b_out -> fp32        [Lq, 256]
    gemm_out<<<dim3(2, mb), 256>>>(p_sampled_h, p_wout2, b_out, out);
}

// round 17
// speedup vs baseline: 1.0221x; 1.0221x over previous
#include <cuda_runtime.h>
#include <cuda_fp16.h>
#include <math.h>
#include <stdint.h>

#define LQ      37440
#define LIN     37440
#define DM      256
#define NHEADS  8
#define CHEAD   32

// scratch (allocation-free per harness rules)
__device__ __half  g_value_h  [LIN * DM];     // [Lin, 256] half (sampler gathers)
__device__ float   g_oa       [LQ * 512];     // [Lq, off(384) | attn(128)] fp32
__device__ __half  g_inflat_h [LIN * DM];     // inflat as half
__device__ __half  g_query_h  [LQ * DM];      // query as half
__device__ __half  g_sampled_h[LQ * DM];      // sampler output as half
__device__ uint32_t g_wv2   [128 * 256];      // W_value  k-pair-interleaved half2
__device__ uint32_t g_woa2  [128 * 512];      // [W_off|W_attn] interleaved half2
__device__ uint32_t g_wout2 [128 * 256];      // W_out interleaved half2
__device__ float   g_boa    [512];            // [b_off ; b_attn]

__device__ __forceinline__ uint32_t pack_h2(float lo, float hi) {
    __half2 h = __floats2half2_rn(lo, hi);
    return *(uint32_t*)&h;
}
__device__ __forceinline__ uint32_t smem_u32(const void* p) {
    uint32_t a;
    asm("{ .reg .u64 t; cvta.to.shared.u64 t, %1; cvt.u32.u64 %0, t; }"
        : "=r"(a) : "l"(p));
    return a;
}
__device__ __forceinline__ void cp_async16(uint32_t dst, const void* src, int srcb) {
    asm volatile("cp.async.cg.shared.global [%0], [%1], 16, %2;"
                 :: "r"(dst), "l"(src), "r"(srcb) : "memory");
}

#define MMA_F16(d, a, b)                                                      \
    asm volatile(                                                             \
        "mma.sync.aligned.m16n8k16.row.col.f32.f16.f16.f32 "                  \
        "{%0,%1,%2,%3}, {%4,%5,%6,%7}, {%8,%9}, {%0,%1,%2,%3};"               \
        : "+f"((d)[0]), "+f"((d)[1]), "+f"((d)[2]), "+f"((d)[3])              \
        : "r"((a)[0]), "r"((a)[1]), "r"((a)[2]), "r"((a)[3]),                 \
          "r"((b)[0]), "r"((b)[1]))

#define PA 20     // A pitch in half2 words (16 + 4) -> conflict-free frags
#define PB 136    // B pitch in half2 words (128 + 8) -> conflict-free frags

// ---------------------------------------------------------------------------
// shared GEMM body: 2-stage cp.async fp16 pipeline (proven R11/R13).
// ---------------------------------------------------------------------------
struct GemmSmem {
    uint32_t As2[2][128 * PA];   // 20.0 KB
    uint32_t Bs2[2][16 * PB];    // 17.0 KB
};

__device__ __forceinline__ void gemm_mainloop(
    GemmSmem* sm, const __half* __restrict__ A, const uint32_t* __restrict__ B2,
    int M, int N, int bm, int bn, float acc[4][4][4])
{
    const int tid  = threadIdx.x;
    const int wid  = tid >> 5;
    const int lane = tid & 31;
    const int g    = lane >> 2;
    const int tg   = lane & 3;
    const int warp_m = (wid >> 2) * 64;
    const int warp_n = (wid & 3) * 32;

    const uint32_t sA = smem_u32(sm->As2);
    const uint32_t sB = smem_u32(sm->Bs2);

    const int amr[2] = { (tid)      >> 2, (tid + 256) >> 2 };
    const int ac4[2] = { (tid & 3) * 4,  (tid & 3) * 4 };
    const int bkr[2] = { (tid)      >> 5, (tid + 256) >> 5 };
    const int bn4[2] = { (tid & 31) * 4, (tid & 31) * 4 };

    #define ISSUE(T, BUF)                                                     \
    do {                                                                      \
        _Pragma("unroll")                                                     \
        for (int i = 0; i < 2; i++) {                                         \
            int gm = bm + amr[i];                                             \
            int srcb = (gm < M) ? 16 : 0;                                     \
            int gmc = (gm < M) ? gm : (M - 1);                                \
            cp_async16(sA + ((BUF) * (128 * PA) + amr[i] * PA + ac4[i]) * 4,  \
                       A + (size_t)gmc * 256 + (T) * 32 + ac4[i] * 2, srcb);  \
            cp_async16(sB + ((BUF) * (16 * PB) + bkr[i] * PB + bn4[i]) * 4,   \
                       B2 + (size_t)((T) * 16 + bkr[i]) * N + bn + bn4[i],    \
                       16);                                                   \
        }                                                                     \
        asm volatile("cp.async.commit_group;" ::: "memory");                  \
    } while (0)

    ISSUE(0, 0);

    #pragma unroll 1
    for (int t = 0; t < 8; t++) {
        if (t < 7) {
            ISSUE(t + 1, (t + 1) & 1);
            asm volatile("cp.async.wait_group 1;" ::: "memory");
        } else {
            asm volatile("cp.async.wait_group 0;" ::: "memory");
        }
        __syncthreads();

        const uint32_t* as = sm->As2[t & 1];
        const uint32_t* bs = sm->Bs2[t & 1];
        #pragma unroll
        for (int ks = 0; ks < 2; ks++) {
            const int kb = ks * 8;
            uint32_t afr[4][4], bfr[4][2];
            #pragma unroll
            for (int mi = 0; mi < 4; mi++) {
                int rb = warp_m + mi * 16 + g;
                afr[mi][0] = as[(rb)     * PA + tg + kb];
                afr[mi][1] = as[(rb + 8) * PA + tg + kb];
                afr[mi][2] = as[(rb)     * PA + tg + 4 + kb];
                afr[mi][3] = as[(rb + 8) * PA + tg + 4 + kb];
            }
            #pragma unroll
            for (int ni = 0; ni < 4; ni++) {
                int col = warp_n + ni * 8 + g;
                bfr[ni][0] = bs[(tg + kb)     * PB + col];
                bfr[ni][1] = bs[(tg + 4 + kb) * PB + col];
            }
            #pragma unroll
            for (int mi = 0; mi < 4; mi++)
                #pragma unroll
                for (int ni = 0; ni < 4; ni++)
                    MMA_F16(acc[mi][ni], afr[mi], bfr[ni]);
        }
        __syncthreads();
    }
    #undef ISSUE
}

__device__ __forceinline__ void gemm_epilogue(
    const float* __restrict__ bias, void* __restrict__ C,
    int M, int N, int bm, int bn, bool half_out, float acc[4][4][4])
{
    const int tid  = threadIdx.x;
    const int wid  = tid >> 5;
    const int lane = tid & 31;
    const int g    = lane >> 2;
    const int tg   = lane & 3;
    const int warp_m = (wid >> 2) * 64;
    const int warp_n = (wid & 3) * 32;

    #pragma unroll
    for (int ni = 0; ni < 4; ni++) {
        const int col = bn + warp_n + ni * 8 + tg * 2;
        const float b0 = bias[col], b1 = bias[col + 1];
        #pragma unroll
        for (int mi = 0; mi < 4; mi++) {
            int r0 = bm + warp_m + mi * 16 + g;
            if (r0 < M) {
                if (half_out)
                    *(uint32_t*)((__half*)C + (size_t)r0 * N + col) =
                        pack_h2(acc[mi][ni][0] + b0, acc[mi][ni][1] + b1);
                else
                    *(float2*)((float*)C + (size_t)r0 * N + col) =
                        make_float2(acc[mi][ni][0] + b0, acc[mi][ni][1] + b1);
            }
            int r1 = r0 + 8;
            if (r1 < M) {
                if (half_out)
                    *(uint32_t*)((__half*)C + (size_t)r1 * N + col) =
                        pack_h2(acc[mi][ni][2] + b0, acc[mi][ni][3] + b1);
                else
                    *(float2*)((float*)C + (size_t)r1 * N + col) =
                        make_float2(acc[mi][ni][2] + b0, acc[mi][ni][3] + b1);
            }
        }
    }
}

// combined front GEMM: blocks x<2 -> value GEMM (half out, N=256),
// x>=2 -> oa GEMM (fp32 out, N=512)
__global__ __launch_bounds__(256, 2) void gemm_front(
    const __half* __restrict__ A1, const uint32_t* __restrict__ B1,
    const float* __restrict__ bias1, __half* __restrict__ C1,
    const __half* __restrict__ A2, const uint32_t* __restrict__ B2,
    const float* __restrict__ bias2, float* __restrict__ C2)
{
    __shared__ GemmSmem sm;
    const bool first = (blockIdx.x < 2);
    const __half*   A    = first ? A1 : A2;
    const uint32_t* B    = first ? B1 : B2;
    const float*    bias = first ? bias1 : bias2;
    void*           C    = first ? (void*)C1 : (void*)C2;
    const int       N    = first ? 256 : 512;
    const int       bn   = (first ? blockIdx.x : (blockIdx.x - 2)) * 128;
    const int       bm   = blockIdx.y * 128;
    const int       M    = LQ;

    float acc[4][4][4];
    #pragma unroll
    for (int i = 0; i < 4; i++)
        #pragma unroll
        for (int j = 0; j < 4; j++)
            #pragma unroll
            for (int r = 0; r < 4; r++) acc[i][j][r] = 0.f;

    gemm_mainloop(&sm, A, B, M, N, bm, bn, acc);
    gemm_epilogue(bias, C, M, N, bm, bn, first, acc);
}

// out GEMM (fp32 out, N=256)
__global__ __launch_bounds__(256, 2) void gemm_out(
    const __half* __restrict__ A, const uint32_t* __restrict__ B2,
    const float* __restrict__ bias, float* __restrict__ C)
{
    __shared__ GemmSmem sm;
    const int bn = blockIdx.x * 128;
    const int bm = blockIdx.y * 128;

    float acc[4][4][4];
    #pragma unroll
    for (int i = 0; i < 4; i++)
        #pragma unroll
        for (int j = 0; j < 4; j++)
            #pragma unroll
            for (int r = 0; r < 4; r++) acc[i][j][r] = 0.f;

    gemm_mainloop(&sm, A, B2, LQ, 256, bm, bn, acc);
    gemm_epilogue(bias, C, LQ, 256, bm, bn, false, acc);
}

// ---------------------------------------------------------------------------
// fused prep kernels
// ---------------------------------------------------------------------------
__global__ __launch_bounds__(256) void f2h_all(
    const float* __restrict__ inflat, const float* __restrict__ query,
    __half* __restrict__ d_inflat, __half* __restrict__ d_query, int n4)
{
    int i = blockIdx.x * 256 + threadIdx.x;
    if (i < n4) {
        float4 v = ((const float4*)inflat)[i];
        ((uint2*)d_inflat)[i] = make_uint2(pack_h2(v.x, v.y), pack_h2(v.z, v.w));
    } else if (i < 2 * n4) {
        int j = i - n4;
        float4 v = ((const float4*)query)[j];
        ((uint2*)d_query)[j] = make_uint2(pack_h2(v.x, v.y), pack_h2(v.z, v.w));
    }
}

__global__ __launch_bounds__(256) void pack_all(
    const float* __restrict__ W_value, const float* __restrict__ W_out,
    const float* __restrict__ W_off,   const float* __restrict__ W_attn,
    const float* __restrict__ b_off,   const float* __restrict__ b_attn,
    uint32_t* __restrict__ wv2, uint32_t* __restrict__ wout2,
    uint32_t* __restrict__ woa2, float* __restrict__ boa)
{
    int i = blockIdx.x * 256 + threadIdx.x;
    if (i < 32768) {                       // W_value: [128][256]
        int k2 = i >> 8, n = i & 255;
        wv2[i] = pack_h2(W_value[(size_t)(2 * k2) * 256 + n],
                         W_value[(size_t)(2 * k2 + 1) * 256 + n]);
    } else if (i < 65536) {                // W_out: [128][256]
        int j = i - 32768;
        int k2 = j >> 8, n = j & 255;
        wout2[j] = pack_h2(W_out[(size_t)(2 * k2) * 256 + n],
                           W_out[(size_t)(2 * k2 + 1) * 256 + n]);
    } else if (i < 131072) {               // W_off|W_attn: [128][512]
        int j = i - 65536;
        int k2 = j >> 9, n = j & 511;
        float a, b;
        if (n < 384) {
            a = W_off[(size_t)(2 * k2) * 384 + n];
            b = W_off[(size_t)(2 * k2 + 1) * 384 + n];
        } else {
            a = W_attn[(size_t)(2 * k2) * 128 + n - 384];
            b = W_attn[(size_t)(2 * k2 + 1) * 128 + n - 384];
        }
        woa2[j] = pack_h2(a, b);
    } else if (i < 131584) {               // bias concat
        int j = i - 131072;
        boa[j] = (j < 384) ? b_off[j] : b_attn[j - 384];
    }
}

// ---------------------------------------------------------------------------
// Sampling: 2 queries/block; dual-query interleaved gather with GROUP-MAJOR
// list layout [h][grp*34 + j] (pitch 34/group, 136/head) -> the gather loads
// 2 contiguous entries per LDS.128 (conflict-free: 68*grp staggers banks by 4).
// Phase-1 mapping: grp = p&3, j = c*4 + (p>>2) (any bijection is legal; sums
// are order-independent).
// ---------------------------------------------------------------------------
#define HP 136   // per-head list pitch in float2 (4 groups x 34)

__global__ __launch_bounds__(256) void sample_kernel(
    const __half* __restrict__ value,   // [Lin, 256] half
    const float* __restrict__ refpts,   // [Lq, 4, 3]
    const float* __restrict__ oa,       // [Lq, 512]: off 0..383, attn 384..511
    __half* __restrict__ sampled)       // [Lq, 256] half
{
    const int q0  = blockIdx.x * 2;
    const int tid = threadIdx.x;
    const unsigned FULL = 0xffffffffu;

    __shared__ float2 s_cwi[2][NHEADS * HP];   // 17.4 KB

    {
        const int qi = tid >> 7;
        const int t  = tid & 127;
        const int q  = q0 + qi;
        const int h  = t >> 4;
        const int p  = t & 15;
        const int l  = p >> 2;
        const int pt = p & 3;

        float logit = oa[(size_t)q * 512 + 384 + t];
        float mx = logit;
        #pragma unroll
        for (int m = 8; m; m >>= 1)
            mx = fmaxf(mx, __shfl_xor_sync(FULL, mx, m));
        float e = __expf(logit - mx);
        float sum = e;
        #pragma unroll
        for (int m = 8; m; m >>= 1)
            sum += __shfl_xor_sync(FULL, sum, m);
        const float wp = e / sum;

        const int   S     = 32 >> l;
        const int   start = (l == 0) ? 0 : (l == 1) ? 32768
                          : (l == 2) ? 36864 : 37376;
        const float fS    = (float)S;

        const float rx = refpts[(size_t)q * 12 + l * 3 + 0];
        const float ry = refpts[(size_t)q * 12 + l * 3 + 1];
        const float rz = refpts[(size_t)q * 12 + l * 3 + 2];

        const size_t ob = (size_t)q * 512 + h * 48 + l * 12 + pt * 3;
        const float ix = fmaf(rx, fS, oa[ob + 0] - 0.5f);
        const float iy = fmaf(ry, fS, oa[ob + 1] - 0.5f);
        const float iz = fmaf(rz, fS, oa[ob + 2] - 0.5f);

        const float x0f = floorf(ix), y0f = floorf(iy), z0f = floorf(iz);
        const float fx = ix - x0f, fy = iy - y0f, fz = iz - z0f;
        const int x0 = (int)x0f, y0 = (int)y0f, z0 = (int)z0f;

        const float wxv[2] = {1.f - fx, fx};
        const float wyv[2] = {1.f - fy, fy};
        const float wzv[2] = {1.f - fz, fz};

        // base for this thread's entries: head h, group p&3, j starts at p>>2
        float2* dst = &s_cwi[qi][h * HP + (p & 3) * 34 + (p >> 2)];

        #pragma unroll
        for (int dz = 0; dz < 2; dz++) {
            const int zc = z0 + dz;
            #pragma unroll
            for (int dy = 0; dy < 2; dy++) {
                const int yc = y0 + dy;
                #pragma unroll
                for (int dx = 0; dx < 2; dx++) {
                    const int xc = x0 + dx;
                    const int c  = dz * 4 + dy * 2 + dx;
                    const bool valid = ((unsigned)xc < (unsigned)S) &
                                       ((unsigned)yc < (unsigned)S) &
                                       ((unsigned)zc < (unsigned)S);
                    float w  = valid ? wp * wzv[dz] * wyv[dy] * wxv[dx] : 0.f;
                    int  idx = valid ? (start + (zc * S + yc) * S + xc) * DM : 0;
                    dst[c * 4] = make_float2(w, __int_as_float(idx));
                }
            }
        }
    }
    __syncthreads();

    const int h    = tid >> 5;
    const int lane = tid & 31;
    const int grp  = lane >> 3;
    const int cg   = lane & 7;
    const __half* vbase = value + h * CHEAD + cg * 4;

    const float2* cw0 = s_cwi[0] + h * HP + grp * 34;
    const float2* cw1 = s_cwi[1] + h * HP + grp * 34;

    float a0x = 0.f, a0y = 0.f, a0z = 0.f, a0w = 0.f;
    float a1x = 0.f, a1y = 0.f, a1z = 0.f, a1w = 0.f;

    #pragma unroll 4
    for (int j2 = 0; j2 < 16; j2++) {
        const float4 ee0 = *(const float4*)(cw0 + 2 * j2);
        const float4 ee1 = *(const float4*)(cw1 + 2 * j2);
        if (ee0.x != 0.f) {
            uint2 u = *(const uint2*)(vbase + __float_as_int(ee0.y));
            float2 v0 = __half22float2(*(__half2*)&u.x);
            float2 v1 = __half22float2(*(__half2*)&u.y);
            a0x = fmaf(ee0.x, v0.x, a0x);
            a0y = fmaf(ee0.x, v0.y, a0y);
            a0z = fmaf(ee0.x, v1.x, a0z);
            a0w = fmaf(ee0.x, v1.y, a0w);
        }
        if (ee1.x != 0.f) {
            uint2 u = *(const uint2*)(vbase + __float_as_int(ee1.y));
            float2 v0 = __half22float2(*(__half2*)&u.x);
            float2 v1 = __half22float2(*(__half2*)&u.y);
            a1x = fmaf(ee1.x, v0.x, a1x);
            a1y = fmaf(ee1.x, v0.y, a1y);
            a1z = fmaf(ee1.x, v1.x, a1z);
            a1w = fmaf(ee1.x, v1.y, a1w);
        }
        if (ee0.z != 0.f) {
            uint2 u = *(const uint2*)(vbase + __float_as_int(ee0.w));
            float2 v0 = __half22float2(*(__half2*)&u.x);
            float2 v1 = __half22float2(*(__half2*)&u.y);
            a0x = fmaf(ee0.z, v0.x, a0x);
            a0y = fmaf(ee0.z, v0.y, a0y);
            a0z = fmaf(ee0.z, v1.x, a0z);
            a0w = fmaf(ee0.z, v1.y, a0w);
        }
        if (ee1.z != 0.f) {
            uint2 u = *(const uint2*)(vbase + __float_as_int(ee1.w));
            float2 v0 = __half22float2(*(__half2*)&u.x);
            float2 v1 = __half22float2(*(__half2*)&u.y);
            a1x = fmaf(ee1.z, v0.x, a1x);
            a1y = fmaf(ee1.z, v0.y, a1y);
            a1z = fmaf(ee1.z, v1.x, a1z);
            a1w = fmaf(ee1.z, v1.y, a1w);
        }
    }

    #pragma unroll
    for (int m = 8; m <= 16; m <<= 1) {
        a0x += __shfl_xor_sync(FULL, a0x, m);
        a0y += __shfl_xor_sync(FULL, a0y, m);
        a0z += __shfl_xor_sync(FULL, a0z, m);
        a0w += __shfl_xor_sync(FULL, a0w, m);
        a1x += __shfl_xor_sync(FULL, a1x, m);
        a1y += __shfl_xor_sync(FULL, a1y, m);
        a1z += __shfl_xor_sync(FULL, a1z, m);
        a1w += __shfl_xor_sync(FULL, a1w, m);
    }
    if (lane < 8) {
        *(uint2*)(sampled + (size_t)q0 * DM + h * CHEAD + cg * 4)
            = make_uint2(pack_h2(a0x, a0y), pack_h2(a0z, a0w));
        *(uint2*)(sampled + (size_t)(q0 + 1) * DM + h * CHEAD + cg * 4)
            = make_uint2(pack_h2(a1x, a1y), pack_h2(a1z, a1w));
    }
}

// ---------------------------------------------------------------------------
extern "C" void kernel_launch(void* const* d_in, const int* in_sizes, int n_in,
                              void* d_out, int out_size)
{
    const float* query   = (const float*)d_in[0];
    const float* refpts  = (const float*)d_in[1];
    const float* inflat  = (const float*)d_in[2];
    const float* W_value = (const float*)d_in[5];
    const float* b_value = (const float*)d_in[6];
    const float* W_off   = (const float*)d_in[7];
    const float* b_off   = (const float*)d_in[8];
    const float* W_attn  = (const float*)d_in[9];
    const float* b_attn  = (const float*)d_in[10];
    const float* W_out   = (const float*)d_in[11];
    const float* b_out   = (const float*)d_in[12];
    float* out = (float*)d_out;

    float *p_oa, *p_boa;
    __half *p_value_h, *p_inflat_h, *p_query_h, *p_sampled_h;
    uint32_t *p_wv2, *p_woa2, *p_wout2;
    cudaGetSymbolAddress((void**)&p_value_h,   g_value_h);
    cudaGetSymbolAddress((void**)&p_oa,        g_oa);
    cudaGetSymbolAddress((void**)&p_inflat_h,  g_inflat_h);
    cudaGetSymbolAddress((void**)&p_query_h,   g_query_h);
    cudaGetSymbolAddress((void**)&p_sampled_h, g_sampled_h);
    cudaGetSymbolAddress((void**)&p_wv2,       g_wv2);
    cudaGetSymbolAddress((void**)&p_woa2,      g_woa2);
    cudaGetSymbolAddress((void**)&p_wout2,     g_wout2);
    cudaGetSymbolAddress((void**)&p_boa,       g_boa);

    const int n4 = LIN * DM / 4;   // 2396160

    f2h_all<<<(2 * n4 + 255) / 256, 256>>>(inflat, query, p_inflat_h, p_query_h, n4);
    pack_all<<<(131584 + 255) / 256, 256>>>(W_value, W_out, W_off, W_attn,
                                            b_off, b_attn,
                                            p_wv2, p_wout2, p_woa2, p_boa);

    const int mb = (LQ + 127) / 128;      // 293

    // value GEMM (half out) + oa GEMM (fp32 out) in one launch
    gemm_front<<<dim3(6, mb), 256>>>(p_inflat_h, p_wv2, b_value, p_value_h,
                                     p_query_h, p_woa2, p_boa, p_oa);
    // softmax + trilinear sampling -> half         [Lq, 256]
    sample_kernel<<<LQ / 2, 256>>>(p_value_h, refpts, p_oa, p_sampled_h);
    // out = sampled @ W_out + b_out -> fp32        [Lq, 256]
    gemm_out<<<dim3(2, mb), 256>>>(p_sampled_h, p_wout2, b_out, out);
}